// round 14
// baseline (speedup 1.0000x reference)
#include <cuda_runtime.h>

// Problem constants (fixed shapes for this problem instance)
#define BB 4
#define NV 8192
#define NF 8192
#define NP 2048
#define MIN_DIST 0.1f

#define CHUNK 128           // faces per shared-memory tile
#define NCHUNK (NF / CHUNK) // 64
#define THREADS 128
#define NPTS 8              // points per thread (scalar FFMA, 8-way ILP)
#define PTS_PER_BLOCK (THREADS * NPTS)        // 1024
#define PBLOCKS (NP / PTS_PER_BLOCK)          // 2
#define TOTAL_BLOCKS (PBLOCKS * NCHUNK * BB)  // 512

// Scratch (no allocations allowed in kernel_launch)
// Face planes: float4 per face = (n'x, n'y, n'z, off')
__device__ float4       g_face[BB * NF];
__device__ unsigned int g_minbits[BB * NP]; // unsigned-min of s-bits over faces
__device__ unsigned int g_ctr;              // last-block counter (reset each run)

__device__ __forceinline__ unsigned int umin2(unsigned int a, unsigned int b) {
    return a < b ? a : b; // IMNMX.U32
}

// ---------------------------------------------------------------------------
// Kernel 1: plane precompute, 4 THREADS PER FACE (c = x,y,z,offset-slot).
// Each thread gathers only its coordinate; dot products via 4-lane shfl.xor.
// Also inits g_minbits (first BB*NP threads). Coalesced float4 component store.
// ---------------------------------------------------------------------------
__global__ __launch_bounds__(256)
void prep_kernel(const float* __restrict__ mesh_V,
                 const float* __restrict__ mesh_FN,
                 const int*   __restrict__ mesh_F) {
    int t = blockIdx.x * blockDim.x + threadIdx.x; // 0 .. BB*NF*4-1
    if (t < BB * NP) g_minbits[t] = 0xFFFFFFFFu;

    int f = t >> 2;        // face id (0 .. BB*NF-1)
    int c = t & 3;         // coordinate lane (3 = offset slot)
    if (f >= BB * NF) return;

    int b = f / NF;
    const int* Fp = mesh_F + 3 * f;
    int i0 = Fp[0], i1 = Fp[1], i2 = Fp[2];
    const float* Vb = mesh_V + (size_t)b * NV * 3;

    float cc = 0.0f, nc = 0.0f;
    if (c < 3) {
        cc = (Vb[3 * i0 + c] + Vb[3 * i1 + c] + Vb[3 * i2 + c]) * (1.0f / 3.0f);
        nc = mesh_FN[3 * f + c];
    }

    // 4-lane group sums (groups are lane-aligned: lanes 4k..4k+3)
    float p  = cc * nc;
    float nn = nc * nc;
    p  += __shfl_xor_sync(0xFFFFFFFFu, p, 1);
    p  += __shfl_xor_sync(0xFFFFFFFFu, p, 2);
    nn += __shfl_xor_sync(0xFFFFFFFFu, nn, 1);
    nn += __shfl_xor_sync(0xFFFFFFFFu, nn, 2);

    float s = sqrtf(nn);
    // s' = ||fn||*(dot(p,fn) - dot(c,fn) + MIN_DIST) => s'^2 == signed^2*fnsq
    float outv = (c == 3) ? (MIN_DIST - p) * s : nc * s;

    ((float*)g_face)[4 * (size_t)f + c] = outv;
}

// ---------------------------------------------------------------------------
// Kernel 2: main loop + fused finalize. grid = (PBLOCKS, NCHUNK, BB), 128 thr.
// Each thread: 8 points, scalar FFMA (FFMA-3reg rt2 — 2x the FLOP rate of
// packed f32x2 FFMA2, which measured at ~quarter rate and was the prior
// ceiling). Per face per thread: 1 LDS.128 + 24 FFMA + 8 IMNMX.
// Unsigned-min over raw float bits: nonneg floats sort as unsigned; negatives
// sort above all nonnegs -> sign bit of result set iff ALL signed dists < 0.
// Last finishing block reduces g_minbits -> scalar mean.
// ---------------------------------------------------------------------------
__global__ __launch_bounds__(THREADS)
void dist_kernel(const float* __restrict__ points,
                 const int*   __restrict__ ext,
                 float*       __restrict__ out) {
    __shared__ float4 sf[CHUNK]; // 2 KB

    const int b   = blockIdx.z;
    const int tid = threadIdx.x;
    const int pb  = blockIdx.x * PTS_PER_BLOCK + tid;

    const float* pp = points + (size_t)b * NP * 3;
    float PX[NPTS], PY[NPTS], PZ[NPTS];
#pragma unroll
    for (int k = 0; k < NPTS; k++) {
        int p = pb + k * THREADS;
        PX[k] = pp[3 * p + 0];
        PY[k] = pp[3 * p + 1];
        PZ[k] = pp[3 * p + 2];
    }

    // tile load: CHUNK float4s, one per thread
    sf[tid] = g_face[(size_t)(b * NF + blockIdx.y * CHUNK) + tid];
    __syncthreads();

    unsigned int m[NPTS];
#pragma unroll
    for (int k = 0; k < NPTS; k++) m[k] = 0xFFFFFFFFu;

#pragma unroll 4
    for (int j = 0; j < CHUNK; j++) {
        float4 f = sf[j]; // LDS.128 broadcast (uniform address)
#pragma unroll
        for (int k = 0; k < NPTS; k++) {
            float s = fmaf(PX[k], f.x, fmaf(PY[k], f.y, fmaf(PZ[k], f.z, f.w)));
            m[k] = umin2(m[k], __float_as_uint(s));
        }
    }

#pragma unroll
    for (int k = 0; k < NPTS; k++)
        atomicMin(&g_minbits[b * NP + pb + k * THREADS], m[k]);

    // ---- last-block-done finalize ----
    __shared__ bool is_last;
    __syncthreads(); // all atomics of this block issued
    if (tid == 0) {
        __threadfence();
        unsigned int done = atomicAdd(&g_ctr, 1u);
        is_last = (done == TOTAL_BLOCKS - 1);
    }
    __syncthreads();
    if (!is_last) return;

    __shared__ float red[THREADS];
    float sum = 0.0f;
#pragma unroll 4
    for (int i = tid; i < BB * NP; i += THREADS) {
        unsigned int bits = __ldcg(&g_minbits[i]); // atomics live in L2
        // sign bit set => every signed distance negative => inside
        bool inside = (ext[i] == 0) || (bits & 0x80000000u);
        float mm = __uint_as_float(bits);
        sum += inside ? 0.0f : mm * mm;
    }
    red[tid] = sum;
    __syncthreads();
#pragma unroll
    for (int s = THREADS / 2; s > 0; s >>= 1) {
        if (tid < s) red[tid] += red[tid + s];
        __syncthreads();
    }
    if (tid == 0) {
        out[0] = red[0] * (1.0f / (float)(BB * NP));
        g_ctr = 0; // restore for next graph replay (deterministic)
    }
}

// ---------------------------------------------------------------------------
extern "C" void kernel_launch(void* const* d_in, const int* in_sizes, int n_in,
                              void* d_out, int out_size) {
    const float* mesh_V  = (const float*)d_in[0];
    const float* points  = (const float*)d_in[1];
    const float* mesh_FN = (const float*)d_in[2];
    const int*   mesh_F  = (const int*)d_in[3];
    const int*   exterior = (const int*)d_in[4];
    float* out = (float*)d_out;

    (void)in_sizes; (void)n_in; (void)out_size;

    prep_kernel<<<(BB * NF * 4 + 255) / 256, 256>>>(mesh_V, mesh_FN, mesh_F);

    dim3 grid(PBLOCKS, NCHUNK, BB);
    dist_kernel<<<grid, THREADS>>>(points, exterior, out);
}